// round 13
// baseline (speedup 1.0000x reference)
#include <cuda_runtime.h>
#include <math.h>

#define HH 1024
#define WW 1024
#define PLANE (HH * WW)

typedef unsigned long long u64;

// Scratch: pass1 output g_sc1[s][x][y] (transposed), pass2 output g_sc2[s][x][y]
// (transposed: pass2 stores its y-pair accumulators directly, coalesced).
__device__ float g_sc1[(size_t)52 * PLANE];
__device__ float g_sc2[(size_t)52 * PLANE];

// ---- packed f32x2 helpers (two independent IEEE-RN lane ops per instr) ----
__device__ __forceinline__ u64 pk2(float v) {
    u64 r; asm("mov.b64 %0, {%1, %1};" : "=l"(r) : "f"(v)); return r;
}
__device__ __forceinline__ u64 fma2(u64 a, u64 b, u64 c) {   // per-lane __fmaf_rn
    u64 d; asm("fma.rn.f32x2 %0, %1, %2, %3;" : "=l"(d) : "l"(a), "l"(b), "l"(c));
    return d;
}
__device__ __forceinline__ u64 mul2(u64 a, u64 b) {          // per-lane __fmul_rn
    u64 d; asm("mul.rn.f32x2 %0, %1, %2;" : "=l"(d) : "l"(a), "l"(b)); return d;
}
__device__ __forceinline__ float lo2(u64 v) { return __uint_as_float((unsigned)v); }
__device__ __forceinline__ float hi2(u64 v) { return __uint_as_float((unsigned)(v >> 32)); }

// ---------------------------------------------------------------------------
// Pass 1: vertical conv, FMA numerics (ascending taps, single accumulator).
// 512 threads, tile 64x x 128y; thread = x-pair (2*tx) x 8 y-outputs (f32x2).
// lenp multiple of 4 (main 8-groups + optional 4-tail, phase 0; pads hit k==0).
// Sigma classes strided (s = c, c+NZ, ...); strip double-buffer by it parity.
// Output transposed to g_sc1[s][x][y] via smem stage.
// ---------------------------------------------------------------------------
__global__ __launch_bounds__(512, 2) void pass1_vert(
    const float* __restrict__ img, const float* __restrict__ k1,
    const float* __restrict__ sigmas, int S, int K, int RMAX, int NZ)
{
    extern __shared__ float sm[];
    float* skb = sm;                       // 2 * 128 kernel strips
    float* simg = sm + 256;                // ROWS * 64
    const int ROWS = 128 + 2 * RMAX + 8;
    float* stage = simg + ROWS * 64;       // 64 * 129 (stage[x][y])

    const int tid = threadIdx.x;
    const int tx = tid & 31, ty = tid >> 5;          // ty in 0..15
    const int x0 = blockIdx.x * 64;
    const int y0 = blockIdx.y * 128;
    const int c = blockIdx.z;                        // sigma stride class

    for (int i = tid; i < 128; i += 512) skb[i] = (i < K) ? k1[c * K + i] : 0.0f;
    for (int i = tid; i < ROWS * 64; i += 512) {
        int rr = i >> 6, cc = i & 63;
        int gy = y0 - RMAX + rr;
        simg[i] = ((unsigned)gy < HH) ? img[gy * WW + x0 + cc] : 0.0f;
    }
    __syncthreads();

    const u64* colp = (const u64*)simg + tx;   // 32 u64 per row

    int it = 0;
    for (int s = c; s < S; s += NZ, ++it) {
        if (s + NZ < S) {
            float* nb = skb + ((it + 1) & 1) * 128;
            for (int i = tid; i < 128; i += 512)
                nb[i] = (i < K) ? k1[(s + NZ) * K + i] : 0.0f;
        }

        float sg = sigmas[s];
        int r = (int)(5.0f * sg + 0.5f) + 1;
        if (r > RMAX) r = RMAX;
        const int lenp = (2 * r + 4) & ~3;          // mult of 4; pads hit k==0
        const int main8 = lenp & ~7;
        const float* kk = skb + (it & 1) * 128 + (RMAX - r);
        const int base = ty * 8 + (RMAX - r);

        u64 w[8], acc[8];
        #pragma unroll
        for (int j = 0; j < 8; ++j) { w[j] = colp[(base + j) * 32]; acc[j] = 0ull; }
        for (int u = 0; u < main8; u += 8) {
            #pragma unroll
            for (int uu = 0; uu < 8; ++uu) {
                u64 kv2 = pk2(kk[u + uu]);
                #pragma unroll
                for (int j = 0; j < 8; ++j)
                    acc[j] = fma2(kv2, w[(uu + j) & 7], acc[j]);
                w[uu] = colp[(base + u + uu + 8) * 32];
            }
        }
        if (lenp & 4) {                 // 4-tap tail; phase 0 (main8 % 8 == 0)
            #pragma unroll
            for (int uu = 0; uu < 4; ++uu) {
                u64 kv2 = pk2(kk[main8 + uu]);
                #pragma unroll
                for (int j = 0; j < 8; ++j)
                    acc[j] = fma2(kv2, w[(uu + j) & 7], acc[j]);
                w[uu] = colp[(base + main8 + uu + 8) * 32];
            }
        }
        __syncthreads();   // prior stage reads done; strip prefetch visible next iter
        #pragma unroll
        for (int j = 0; j < 8; ++j) {
            stage[(2 * tx + 0) * 129 + ty * 8 + j] = lo2(acc[j]);
            stage[(2 * tx + 1) * 129 + ty * 8 + j] = hi2(acc[j]);
        }
        __syncthreads();
        float* op = g_sc1 + (size_t)s * PLANE + (size_t)x0 * HH + y0;
        for (int e = tid; e < 8192; e += 512) {
            int xo = e >> 7, yo = e & 127;   // consecutive e -> consecutive yo
            op[(size_t)xo * HH + yo] = stage[xo * 129 + yo];
        }
    }
}

// ---------------------------------------------------------------------------
// Pass 2: horizontal conv on transposed planes, STRICT mul-then-add numerics
// (two roundings per tap):
//   p   = mul.rn.f32x2(k, x)        == rn(k*x)
//   acc = fma.rn.f32x2(p, one, acc) == rn(acc + p) (x1 exact; FMA consumer =>
//                                                   no mul+add contraction)
// one is a runtime arg so ptxas cannot fold the FMA into an ADD.
// NO output stage: acc[j] lanes span 64 consecutive y at fixed x, stored
// directly (coalesced STG.64) into transposed g_sc2[s][x][y].
// grid.x = x-tile so adjacent-dispatched blocks share halo in L2.
// ---------------------------------------------------------------------------
__global__ __launch_bounds__(512, 2) void pass2_horiz(
    const float* __restrict__ k1, const float* __restrict__ sigmas,
    int S, int K, int RMAX, float zero_rt, float one_rt)
{
    extern __shared__ float sm[];
    float* sk = sm;                        // 128
    float* stile = sm + 128;               // (128 + 2*RMAX + 8) * 64

    const int tid = threadIdx.x;
    const int tx = tid & 31, ty = tid >> 5;
    const int x0 = blockIdx.x * 128;  // conv dim (fastest: halo L2 reuse)
    const int y0 = blockIdx.y * 64;   // minor dim of transposed layout
    const int s = blockIdx.z;

    const u64 zero2 = pk2(zero_rt);
    const u64 one2 = pk2(one_rt);

    float sg = sigmas[s];
    int r = (int)(5.0f * sg + 0.5f) + 1;
    if (r > RMAX) r = RMAX;

    for (int i = tid; i < 128; i += 512) sk[i] = (i < K) ? k1[s * K + i] : 0.0f;

    const int ROWS = 128 + 2 * r + 8;
    const float* ip = g_sc1 + (size_t)s * PLANE;
    for (int i = tid; i < ROWS * 64; i += 512) {
        int rr = i >> 6, cc = i & 63;
        int gx = x0 - r + rr;
        stile[i] = ((unsigned)gx < WW) ? ip[(size_t)gx * HH + y0 + cc] : 0.0f;
    }
    __syncthreads();

    const u64* colp = (const u64*)stile + tx;
    const float* kk = sk + (RMAX - r);
    const int base = ty * 8;
    const int lenp = (2 * r + 4) & ~3;
    const int main8 = lenp & ~7;

    u64 w[8], acc[8];
    #pragma unroll
    for (int j = 0; j < 8; ++j) { w[j] = colp[(base + j) * 32]; acc[j] = zero2; }
    for (int u = 0; u < main8; u += 8) {
        #pragma unroll
        for (int uu = 0; uu < 8; ++uu) {
            u64 kv2 = pk2(kk[u + uu]);
            #pragma unroll
            for (int j = 0; j < 8; ++j) {
                u64 p = mul2(kv2, w[(uu + j) & 7]);          // rn(k*x)
                acc[j] = fma2(p, one2, acc[j]);              // rn(acc + p)
            }
            w[uu] = colp[(base + u + uu + 8) * 32];
        }
    }
    if (lenp & 4) {                     // 4-tap tail; phase 0
        #pragma unroll
        for (int uu = 0; uu < 4; ++uu) {
            u64 kv2 = pk2(kk[main8 + uu]);
            #pragma unroll
            for (int j = 0; j < 8; ++j) {
                u64 p = mul2(kv2, w[(uu + j) & 7]);          // rn(k*x)
                acc[j] = fma2(p, one2, acc[j]);              // rn(acc + p)
            }
            w[uu] = colp[(base + main8 + uu + 8) * 32];
        }
    }
    // direct coalesced stores: lanes span 64 y, fixed x = x0 + base + j
    float* op = g_sc2 + (size_t)s * PLANE;
    #pragma unroll
    for (int j = 0; j < 8; ++j) {
        size_t off = (size_t)(x0 + base + j) * HH + y0 + 2 * tx;
        *(u64*)&op[off] = acc[j];
    }
}

// ---------------------------------------------------------------------------
// Pass 3: fused DoG + 3x3x3 maxpool (pad -inf) + mask, rolling over scale s.
// Source planes TRANSPOSED ([s][x][y]): loads are yy-inner (coalesced),
// smem tiles un-transposed with stride 37 (odd => conflict-free).
// ---------------------------------------------------------------------------
__global__ __launch_bounds__(256) void pass3_dog_nms(
    const float* __restrict__ sigmas, float* __restrict__ out,
    int S, size_t out_n)
{
    __shared__ float gb[2][34 * 37];
    __shared__ float db[2][34 * 37];
    __shared__ float m2[3][1024];

    const int tid = threadIdx.x;
    const int x0 = blockIdx.x * 32 - 1;
    const int y0 = blockIdx.y * 32 - 1;
    const float NINF = -INFINITY;
    const size_t n1 = (size_t)(S - 1) * PLANE;

    for (int i = tid; i < 3 * 1024; i += 256) (&m2[0][0])[i] = NINF;

    for (int s = 0; s <= S; ++s) {
        if (s < S) {
            const float* gp = g_sc2 + (size_t)s * PLANE;   // [x][y]
            for (int i = tid; i < 34 * 34; i += 256) {
                int xx = i / 34, yy = i - xx * 34;   // yy inner: coalesced gmem
                int gy = y0 + yy, gx = x0 + xx;
                gb[s & 1][yy * 37 + xx] =
                    ((unsigned)gy < HH && (unsigned)gx < WW)
                        ? gp[(size_t)gx * HH + gy] : 0.0f;
            }
        }
        __syncthreads();
        if (s >= 1 && s < S) {
            float sg = sigmas[s - 1];
            for (int i = tid; i < 34 * 34; i += 256) {
                int xx = i / 34, yy = i - xx * 34;
                int gy = y0 + yy, gx = x0 + xx;
                float v = NINF;  // -inf outside image: matches maxpool padding
                if ((unsigned)gy < HH && (unsigned)gx < WW)
                    v = __fmul_rn(__fsub_rn(gb[(s - 1) & 1][yy * 37 + xx],
                                            gb[s & 1][yy * 37 + xx]), sg);
                db[(s - 1) & 1][yy * 37 + xx] = v;
            }
        } else if (s == S) {
            for (int i = tid; i < 1024; i += 256) m2[(S - 1) % 3][i] = NINF;
        }
        __syncthreads();
        if (s >= 1 && s < S) {
            int d = s - 1;
            const float* dp0 = &db[d & 1][0];
            for (int i = tid; i < 1024; i += 256) {
                int yy = i >> 5, xx = i & 31;
                const float* dp = dp0 + yy * 37 + xx;
                float m = fmaxf(fmaxf(dp[0], dp[1]), dp[2]);
                m = fmaxf(m, fmaxf(fmaxf(dp[37], dp[38]), dp[39]));
                m = fmaxf(m, fmaxf(fmaxf(dp[74], dp[75]), dp[76]));
                m2[d % 3][i] = m;
            }
        }
        __syncthreads();
        if (s >= 2) {
            int t = s - 2;
            for (int i = tid; i < 1024; i += 256) {
                int yy = i >> 5, xx = i & 31;
                float dv = db[t & 1][(yy + 1) * 37 + (xx + 1)];
                float p = fmaxf(fmaxf(m2[(t + 2) % 3][i], m2[t % 3][i]),
                                m2[(t + 1) % 3][i]);
                int gy = y0 + 1 + yy, gx = x0 + 1 + xx;
                size_t oidx = (size_t)t * PLANE + (size_t)gy * WW + gx;
                if (oidx < out_n) out[oidx] = dv;
                size_t midx = n1 + oidx;
                if (midx < out_n)
                    out[midx] = (dv == p && dv > 0.001f) ? 1.0f : 0.0f;
            }
        }
        __syncthreads();
    }
}

__global__ void zero_tail(float* p, size_t n)
{
    size_t i = (size_t)blockIdx.x * blockDim.x + threadIdx.x;
    if (i < n) p[i] = 0.0f;
}

extern "C" void kernel_launch(void* const* d_in, const int* in_sizes, int n_in,
                              void* d_out, int out_size)
{
    const float* img = (const float*)d_in[0];
    const float* k1  = (const float*)d_in[1];
    const float* sig = (const float*)d_in[2];
    int S = in_sizes[2];               // number of sigmas
    int K = in_sizes[1] / S;           // padded 1D kernel length
    int RMAX = (K - 1) / 2;
    float* out = (float*)d_out;
    size_t n1 = (size_t)(S - 1) * PLANE;
    size_t used = 2 * n1;
    size_t on = (size_t)out_size;

    int rows = 128 + 2 * RMAX + 8;
    size_t smem1 = (size_t)(256 + rows * 64 + 64 * 129) * sizeof(float);
    size_t smem2 = (size_t)(128 + rows * 64) * sizeof(float);
    cudaFuncSetAttribute(pass1_vert, cudaFuncAttributeMaxDynamicSharedMemorySize,
                         (int)smem1);
    cudaFuncSetAttribute(pass2_horiz, cudaFuncAttributeMaxDynamicSharedMemorySize,
                         (int)smem2);

    const int NZ = 8;                  // strided sigma classes
    dim3 g1(WW / 64, HH / 128, NZ);
    pass1_vert<<<g1, 512, smem1>>>(img, k1, sig, S, K, RMAX, NZ);

    // zero_rt/one_rt as runtime args: opaque to constant folding.
    volatile float z = 0.0f, o = 1.0f;
    dim3 g2(WW / 128, HH / 64, S);     // x-tile fastest: halo L2 reuse
    pass2_horiz<<<g2, 512, smem2>>>(k1, sig, S, K, RMAX, z, o);

    dim3 g3(WW / 32, HH / 32);
    pass3_dog_nms<<<g3, 256>>>(sig, out, S, on);

    if (on > used) {
        size_t rem = on - used;
        int blocks = (int)((rem + 255) / 256);
        zero_tail<<<blocks, 256>>>(out + used, rem);
    }
}

// round 14
// speedup vs baseline: 1.1668x; 1.1668x over previous
#include <cuda_runtime.h>
#include <math.h>

#define HH 1024
#define WW 1024
#define PLANE (HH * WW)

typedef unsigned long long u64;

// Scratch: pass1 output (transposed, [s][x][y]) and pass2 output ([s][y][x]).
__device__ float g_sc1[(size_t)52 * PLANE];
__device__ float g_sc2[(size_t)52 * PLANE];

// ---- packed f32x2 helpers (two independent IEEE-RN lane ops per instr) ----
__device__ __forceinline__ u64 pk2(float v) {
    u64 r; asm("mov.b64 %0, {%1, %1};" : "=l"(r) : "f"(v)); return r;
}
__device__ __forceinline__ u64 fma2(u64 a, u64 b, u64 c) {   // per-lane __fmaf_rn
    u64 d; asm("fma.rn.f32x2 %0, %1, %2, %3;" : "=l"(d) : "l"(a), "l"(b), "l"(c));
    return d;
}
__device__ __forceinline__ u64 mul2(u64 a, u64 b) {          // per-lane __fmul_rn
    u64 d; asm("mul.rn.f32x2 %0, %1, %2;" : "=l"(d) : "l"(a), "l"(b)); return d;
}
__device__ __forceinline__ float lo2(u64 v) { return __uint_as_float((unsigned)v); }
__device__ __forceinline__ float hi2(u64 v) { return __uint_as_float((unsigned)(v >> 32)); }

// ---------------------------------------------------------------------------
// Pass 1: vertical conv, FMA numerics (ascending taps, single accumulator).
// 512 threads, tile 64x x 128y; thread = x-pair (2*tx) x 8 y-outputs (f32x2).
// lenp multiple of 4 (main 8-groups + optional 4-tail, phase 0; pads hit k==0).
// Sigma classes strided (s = c, c+NZ, ...); strip double-buffer by it parity.
// Output transposed to g_sc1[s][x][y] via smem stage.
// ---------------------------------------------------------------------------
__global__ __launch_bounds__(512, 2) void pass1_vert(
    const float* __restrict__ img, const float* __restrict__ k1,
    const float* __restrict__ sigmas, int S, int K, int RMAX, int NZ)
{
    extern __shared__ float sm[];
    float* skb = sm;                       // 2 * 128 kernel strips
    float* simg = sm + 256;                // ROWS * 64
    const int ROWS = 128 + 2 * RMAX + 8;
    float* stage = simg + ROWS * 64;       // 64 * 129 (stage[x][y])

    const int tid = threadIdx.x;
    const int tx = tid & 31, ty = tid >> 5;          // ty in 0..15
    const int x0 = blockIdx.x * 64;
    const int y0 = blockIdx.y * 128;
    const int c = blockIdx.z;                        // sigma stride class

    for (int i = tid; i < 128; i += 512) skb[i] = (i < K) ? k1[c * K + i] : 0.0f;
    for (int i = tid; i < ROWS * 64; i += 512) {
        int rr = i >> 6, cc = i & 63;
        int gy = y0 - RMAX + rr;
        simg[i] = ((unsigned)gy < HH) ? img[gy * WW + x0 + cc] : 0.0f;
    }
    __syncthreads();

    const u64* colp = (const u64*)simg + tx;   // 32 u64 per row

    int it = 0;
    for (int s = c; s < S; s += NZ, ++it) {
        if (s + NZ < S) {
            float* nb = skb + ((it + 1) & 1) * 128;
            for (int i = tid; i < 128; i += 512)
                nb[i] = (i < K) ? k1[(s + NZ) * K + i] : 0.0f;
        }

        float sg = sigmas[s];
        int r = (int)(5.0f * sg + 0.5f) + 1;
        if (r > RMAX) r = RMAX;
        const int lenp = (2 * r + 4) & ~3;          // mult of 4; pads hit k==0
        const int main8 = lenp & ~7;
        const float* kk = skb + (it & 1) * 128 + (RMAX - r);
        const int base = ty * 8 + (RMAX - r);

        u64 w[8], acc[8];
        #pragma unroll
        for (int j = 0; j < 8; ++j) { w[j] = colp[(base + j) * 32]; acc[j] = 0ull; }
        for (int u = 0; u < main8; u += 8) {
            #pragma unroll
            for (int uu = 0; uu < 8; ++uu) {
                u64 kv2 = pk2(kk[u + uu]);
                #pragma unroll
                for (int j = 0; j < 8; ++j)
                    acc[j] = fma2(kv2, w[(uu + j) & 7], acc[j]);
                w[uu] = colp[(base + u + uu + 8) * 32];
            }
        }
        if (lenp & 4) {                 // 4-tap tail; phase 0 (main8 % 8 == 0)
            #pragma unroll
            for (int uu = 0; uu < 4; ++uu) {
                u64 kv2 = pk2(kk[main8 + uu]);
                #pragma unroll
                for (int j = 0; j < 8; ++j)
                    acc[j] = fma2(kv2, w[(uu + j) & 7], acc[j]);
                w[uu] = colp[(base + main8 + uu + 8) * 32];
            }
        }
        __syncthreads();   // prior stage reads done; strip prefetch visible next iter
        #pragma unroll
        for (int j = 0; j < 8; ++j) {
            stage[(2 * tx + 0) * 129 + ty * 8 + j] = lo2(acc[j]);
            stage[(2 * tx + 1) * 129 + ty * 8 + j] = hi2(acc[j]);
        }
        __syncthreads();
        float* op = g_sc1 + (size_t)s * PLANE + (size_t)x0 * HH + y0;
        for (int e = tid; e < 8192; e += 512) {
            int xo = e >> 7, yo = e & 127;   // consecutive e -> consecutive yo
            op[(size_t)xo * HH + yo] = stage[xo * 129 + yo];
        }
    }
}

// ---------------------------------------------------------------------------
// Pass 2: horizontal conv on transposed planes, STRICT mul-then-add numerics
// (two roundings per tap):
//   p   = mul.rn.f32x2(k, x)        == rn(k*x)
//   acc = fma.rn.f32x2(p, one, acc) == rn(acc + p) (x1 exact; FMA consumer =>
//                                                   no mul+add contraction)
// one is a runtime arg so ptxas cannot fold the FMA into an ADD.
// 512 threads; tile 64 minor(y) x 128 conv(x); thread = y-pair x 8 x-outputs.
// Output [s][y][x] via smem stage (R12 structure). blockIdx.x = x-tile so
// consecutively-dispatched blocks share the x-halo in L2.
// ---------------------------------------------------------------------------
__global__ __launch_bounds__(512, 2) void pass2_horiz(
    const float* __restrict__ k1, const float* __restrict__ sigmas,
    int S, int K, int RMAX, float zero_rt, float one_rt)
{
    extern __shared__ float sm[];
    float* sk = sm;                        // 128
    float* stile = sm + 128;               // (128 + 2*RMAX + 8) * 64
    float* stage = stile + (128 + 2 * RMAX + 8) * 64;  // 64 * 129 (stage[y][x])

    const int tid = threadIdx.x;
    const int tx = tid & 31, ty = tid >> 5;
    const int x0 = blockIdx.x * 128;  // conv dim (fastest: halo L2 reuse)
    const int y0 = blockIdx.y * 64;   // minor dim of transposed layout
    const int s = blockIdx.z;

    const u64 zero2 = pk2(zero_rt);
    const u64 one2 = pk2(one_rt);

    float sg = sigmas[s];
    int r = (int)(5.0f * sg + 0.5f) + 1;
    if (r > RMAX) r = RMAX;

    for (int i = tid; i < 128; i += 512) sk[i] = (i < K) ? k1[s * K + i] : 0.0f;

    const int ROWS = 128 + 2 * r + 8;
    const float* ip = g_sc1 + (size_t)s * PLANE;
    for (int i = tid; i < ROWS * 64; i += 512) {
        int rr = i >> 6, cc = i & 63;
        int gx = x0 - r + rr;
        stile[i] = ((unsigned)gx < WW) ? ip[(size_t)gx * HH + y0 + cc] : 0.0f;
    }
    __syncthreads();

    const u64* colp = (const u64*)stile + tx;
    const float* kk = sk + (RMAX - r);
    const int base = ty * 8;
    const int lenp = (2 * r + 4) & ~3;
    const int main8 = lenp & ~7;

    u64 w[8], acc[8];
    #pragma unroll
    for (int j = 0; j < 8; ++j) { w[j] = colp[(base + j) * 32]; acc[j] = zero2; }
    for (int u = 0; u < main8; u += 8) {
        #pragma unroll
        for (int uu = 0; uu < 8; ++uu) {
            u64 kv2 = pk2(kk[u + uu]);
            #pragma unroll
            for (int j = 0; j < 8; ++j) {
                u64 p = mul2(kv2, w[(uu + j) & 7]);          // rn(k*x)
                acc[j] = fma2(p, one2, acc[j]);              // rn(acc + p)
            }
            w[uu] = colp[(base + u + uu + 8) * 32];
        }
    }
    if (lenp & 4) {                     // 4-tap tail; phase 0
        #pragma unroll
        for (int uu = 0; uu < 4; ++uu) {
            u64 kv2 = pk2(kk[main8 + uu]);
            #pragma unroll
            for (int j = 0; j < 8; ++j) {
                u64 p = mul2(kv2, w[(uu + j) & 7]);          // rn(k*x)
                acc[j] = fma2(p, one2, acc[j]);              // rn(acc + p)
            }
            w[uu] = colp[(base + main8 + uu + 8) * 32];
        }
    }
    #pragma unroll
    for (int j = 0; j < 8; ++j) {
        stage[(2 * tx + 0) * 129 + ty * 8 + j] = lo2(acc[j]);
        stage[(2 * tx + 1) * 129 + ty * 8 + j] = hi2(acc[j]);
    }
    __syncthreads();
    float* op = g_sc2 + (size_t)s * PLANE + (size_t)y0 * WW + x0;
    for (int e = tid; e < 8192; e += 512) {
        int yo = e >> 7, xo = e & 127;   // consecutive e -> consecutive xo
        op[(size_t)yo * WW + xo] = stage[yo * 129 + xo];
    }
}

// ---------------------------------------------------------------------------
// Pass 3: fused DoG + 3x3x3 maxpool (pad -inf) + mask, rolling over scale s.
// ---------------------------------------------------------------------------
__global__ __launch_bounds__(256) void pass3_dog_nms(
    const float* __restrict__ sigmas, float* __restrict__ out,
    int S, size_t out_n)
{
    __shared__ float gb[2][34 * 36];
    __shared__ float db[2][34 * 36];
    __shared__ float m2[3][1024];

    const int tid = threadIdx.x;
    const int x0 = blockIdx.x * 32 - 1;
    const int y0 = blockIdx.y * 32 - 1;
    const float NINF = -INFINITY;
    const size_t n1 = (size_t)(S - 1) * PLANE;

    for (int i = tid; i < 3 * 1024; i += 256) (&m2[0][0])[i] = NINF;

    for (int s = 0; s <= S; ++s) {
        if (s < S) {
            const float* gp = g_sc2 + (size_t)s * PLANE;
            for (int i = tid; i < 34 * 34; i += 256) {
                int yy = i / 34, xx = i - yy * 34;
                int gy = y0 + yy, gx = x0 + xx;
                gb[s & 1][yy * 36 + xx] =
                    ((unsigned)gy < HH && (unsigned)gx < WW) ? gp[gy * WW + gx] : 0.0f;
            }
        }
        __syncthreads();
        if (s >= 1 && s < S) {
            float sg = sigmas[s - 1];
            for (int i = tid; i < 34 * 34; i += 256) {
                int yy = i / 34, xx = i - yy * 34;
                int gy = y0 + yy, gx = x0 + xx;
                float v = NINF;  // -inf outside image: matches maxpool padding
                if ((unsigned)gy < HH && (unsigned)gx < WW)
                    v = __fmul_rn(__fsub_rn(gb[(s - 1) & 1][yy * 36 + xx],
                                            gb[s & 1][yy * 36 + xx]), sg);
                db[(s - 1) & 1][yy * 36 + xx] = v;
            }
        } else if (s == S) {
            for (int i = tid; i < 1024; i += 256) m2[(S - 1) % 3][i] = NINF;
        }
        __syncthreads();
        if (s >= 1 && s < S) {
            int d = s - 1;
            const float* dp0 = &db[d & 1][0];
            for (int i = tid; i < 1024; i += 256) {
                int yy = i >> 5, xx = i & 31;
                const float* dp = dp0 + yy * 36 + xx;
                float m = fmaxf(fmaxf(dp[0], dp[1]), dp[2]);
                m = fmaxf(m, fmaxf(fmaxf(dp[36], dp[37]), dp[38]));
                m = fmaxf(m, fmaxf(fmaxf(dp[72], dp[73]), dp[74]));
                m2[d % 3][i] = m;
            }
        }
        __syncthreads();
        if (s >= 2) {
            int t = s - 2;
            for (int i = tid; i < 1024; i += 256) {
                int yy = i >> 5, xx = i & 31;
                float dv = db[t & 1][(yy + 1) * 36 + (xx + 1)];
                float p = fmaxf(fmaxf(m2[(t + 2) % 3][i], m2[t % 3][i]),
                                m2[(t + 1) % 3][i]);
                int gy = y0 + 1 + yy, gx = x0 + 1 + xx;
                size_t oidx = (size_t)t * PLANE + (size_t)gy * WW + gx;
                if (oidx < out_n) out[oidx] = dv;
                size_t midx = n1 + oidx;
                if (midx < out_n)
                    out[midx] = (dv == p && dv > 0.001f) ? 1.0f : 0.0f;
            }
        }
        __syncthreads();
    }
}

__global__ void zero_tail(float* p, size_t n)
{
    size_t i = (size_t)blockIdx.x * blockDim.x + threadIdx.x;
    if (i < n) p[i] = 0.0f;
}

extern "C" void kernel_launch(void* const* d_in, const int* in_sizes, int n_in,
                              void* d_out, int out_size)
{
    const float* img = (const float*)d_in[0];
    const float* k1  = (const float*)d_in[1];
    const float* sig = (const float*)d_in[2];
    int S = in_sizes[2];               // number of sigmas
    int K = in_sizes[1] / S;           // padded 1D kernel length
    int RMAX = (K - 1) / 2;
    float* out = (float*)d_out;
    size_t n1 = (size_t)(S - 1) * PLANE;
    size_t used = 2 * n1;
    size_t on = (size_t)out_size;

    int rows = 128 + 2 * RMAX + 8;
    size_t smem1 = (size_t)(256 + rows * 64 + 64 * 129) * sizeof(float);
    size_t smem2 = (size_t)(128 + rows * 64 + 64 * 129) * sizeof(float);
    cudaFuncSetAttribute(pass1_vert, cudaFuncAttributeMaxDynamicSharedMemorySize,
                         (int)smem1);
    cudaFuncSetAttribute(pass2_horiz, cudaFuncAttributeMaxDynamicSharedMemorySize,
                         (int)smem2);

    const int NZ = 7;                  // 896 blocks = 3.03 waves at 2/SM
    dim3 g1(WW / 64, HH / 128, NZ);
    pass1_vert<<<g1, 512, smem1>>>(img, k1, sig, S, K, RMAX, NZ);

    // zero_rt/one_rt as runtime args: opaque to constant folding.
    volatile float z = 0.0f, o = 1.0f;
    dim3 g2(WW / 128, HH / 64, S);     // x-tile fastest: halo L2 reuse
    pass2_horiz<<<g2, 512, smem2>>>(k1, sig, S, K, RMAX, z, o);

    dim3 g3(WW / 32, HH / 32);
    pass3_dog_nms<<<g3, 256>>>(sig, out, S, on);

    if (on > used) {
        size_t rem = on - used;
        int blocks = (int)((rem + 255) / 256);
        zero_tail<<<blocks, 256>>>(out + used, rem);
    }
}

// round 15
// speedup vs baseline: 1.1927x; 1.0222x over previous
#include <cuda_runtime.h>
#include <math.h>

#define HH 1024
#define WW 1024
#define PLANE (HH * WW)

typedef unsigned long long u64;

// Scratch: pass1 output (transposed, [s][x][y]) and pass2 output ([s][y][x]).
__device__ float g_sc1[(size_t)52 * PLANE];
__device__ float g_sc2[(size_t)52 * PLANE];

// ---- packed f32x2 helpers (two independent IEEE-RN lane ops per instr) ----
__device__ __forceinline__ u64 pk2(float v) {
    u64 r; asm("mov.b64 %0, {%1, %1};" : "=l"(r) : "f"(v)); return r;
}
__device__ __forceinline__ u64 fma2(u64 a, u64 b, u64 c) {   // per-lane __fmaf_rn
    u64 d; asm("fma.rn.f32x2 %0, %1, %2, %3;" : "=l"(d) : "l"(a), "l"(b), "l"(c));
    return d;
}
__device__ __forceinline__ u64 mul2(u64 a, u64 b) {          // per-lane __fmul_rn
    u64 d; asm("mul.rn.f32x2 %0, %1, %2;" : "=l"(d) : "l"(a), "l"(b)); return d;
}
__device__ __forceinline__ float lo2(u64 v) { return __uint_as_float((unsigned)v); }
__device__ __forceinline__ float hi2(u64 v) { return __uint_as_float((unsigned)(v >> 32)); }

// ---------------------------------------------------------------------------
// Pass 1: vertical conv, FMA numerics (ascending taps, single accumulator).
// 512 threads, tile 64x x 128y; thread = x-pair (2*tx) x 8 y-outputs (f32x2).
// lenp multiple of 4 (main 8-groups + optional 4-tail, phase 0; pads hit k==0).
// Sigma classes strided (s = c, c+NZ, ...); strip double-buffer by it parity.
// Output transposed to g_sc1[s][x][y] via smem stage.
// ---------------------------------------------------------------------------
__global__ __launch_bounds__(512, 2) void pass1_vert(
    const float* __restrict__ img, const float* __restrict__ k1,
    const float* __restrict__ sigmas, int S, int K, int RMAX, int NZ)
{
    extern __shared__ float sm[];
    float* skb = sm;                       // 2 * 128 kernel strips
    float* simg = sm + 256;                // ROWS * 64
    const int ROWS = 128 + 2 * RMAX + 8;
    float* stage = simg + ROWS * 64;       // 64 * 129 (stage[x][y])

    const int tid = threadIdx.x;
    const int tx = tid & 31, ty = tid >> 5;          // ty in 0..15
    const int x0 = blockIdx.x * 64;
    const int y0 = blockIdx.y * 128;
    const int c = blockIdx.z;                        // sigma stride class

    for (int i = tid; i < 128; i += 512) skb[i] = (i < K) ? k1[c * K + i] : 0.0f;
    for (int i = tid; i < ROWS * 64; i += 512) {
        int rr = i >> 6, cc = i & 63;
        int gy = y0 - RMAX + rr;
        simg[i] = ((unsigned)gy < HH) ? img[gy * WW + x0 + cc] : 0.0f;
    }
    __syncthreads();

    const u64* colp = (const u64*)simg + tx;   // 32 u64 per row

    int it = 0;
    for (int s = c; s < S; s += NZ, ++it) {
        if (s + NZ < S) {
            float* nb = skb + ((it + 1) & 1) * 128;
            for (int i = tid; i < 128; i += 512)
                nb[i] = (i < K) ? k1[(s + NZ) * K + i] : 0.0f;
        }

        float sg = sigmas[s];
        int r = (int)(5.0f * sg + 0.5f) + 1;
        if (r > RMAX) r = RMAX;
        const int lenp = (2 * r + 4) & ~3;          // mult of 4; pads hit k==0
        const int main8 = lenp & ~7;
        const float* kk = skb + (it & 1) * 128 + (RMAX - r);
        const int base = ty * 8 + (RMAX - r);

        u64 w[8], acc[8];
        #pragma unroll
        for (int j = 0; j < 8; ++j) { w[j] = colp[(base + j) * 32]; acc[j] = 0ull; }
        for (int u = 0; u < main8; u += 8) {
            #pragma unroll
            for (int uu = 0; uu < 8; ++uu) {
                u64 kv2 = pk2(kk[u + uu]);
                #pragma unroll
                for (int j = 0; j < 8; ++j)
                    acc[j] = fma2(kv2, w[(uu + j) & 7], acc[j]);
                w[uu] = colp[(base + u + uu + 8) * 32];
            }
        }
        if (lenp & 4) {                 // 4-tap tail; phase 0 (main8 % 8 == 0)
            #pragma unroll
            for (int uu = 0; uu < 4; ++uu) {
                u64 kv2 = pk2(kk[main8 + uu]);
                #pragma unroll
                for (int j = 0; j < 8; ++j)
                    acc[j] = fma2(kv2, w[(uu + j) & 7], acc[j]);
                w[uu] = colp[(base + main8 + uu + 8) * 32];
            }
        }
        __syncthreads();   // prior stage reads done; strip prefetch visible next iter
        #pragma unroll
        for (int j = 0; j < 8; ++j) {
            stage[(2 * tx + 0) * 129 + ty * 8 + j] = lo2(acc[j]);
            stage[(2 * tx + 1) * 129 + ty * 8 + j] = hi2(acc[j]);
        }
        __syncthreads();
        float* op = g_sc1 + (size_t)s * PLANE + (size_t)x0 * HH + y0;
        for (int e = tid; e < 8192; e += 512) {
            int xo = e >> 7, yo = e & 127;   // consecutive e -> consecutive yo
            op[(size_t)xo * HH + yo] = stage[xo * 129 + yo];
        }
    }
}

// ---------------------------------------------------------------------------
// Pass 2: horizontal conv on transposed planes, STRICT mul-then-add numerics
// (two roundings per tap):
//   p   = mul.rn.f32x2(k, x)        == rn(k*x)
//   acc = fma.rn.f32x2(p, one, acc) == rn(acc + p) (x1 exact; FMA consumer =>
//                                                   no mul+add contraction)
// one is a runtime arg so ptxas cannot fold the FMA into an ADD.
// 512 threads; tile 64 minor(y) x 128 conv(x); thread = y-pair x 8 x-outputs.
// Output [s][y][x] via smem stage. R12 grid order (y-tile fastest).
// ---------------------------------------------------------------------------
__global__ __launch_bounds__(512, 2) void pass2_horiz(
    const float* __restrict__ k1, const float* __restrict__ sigmas,
    int S, int K, int RMAX, float zero_rt, float one_rt)
{
    extern __shared__ float sm[];
    float* sk = sm;                        // 128
    float* stile = sm + 128;               // (128 + 2*RMAX + 8) * 64
    float* stage = stile + (128 + 2 * RMAX + 8) * 64;  // 64 * 129 (stage[y][x])

    const int tid = threadIdx.x;
    const int tx = tid & 31, ty = tid >> 5;
    const int y0 = blockIdx.x * 64;   // minor dim of transposed layout
    const int x0 = blockIdx.y * 128;  // conv dim
    const int s = blockIdx.z;

    const u64 zero2 = pk2(zero_rt);
    const u64 one2 = pk2(one_rt);

    float sg = sigmas[s];
    int r = (int)(5.0f * sg + 0.5f) + 1;
    if (r > RMAX) r = RMAX;

    for (int i = tid; i < 128; i += 512) sk[i] = (i < K) ? k1[s * K + i] : 0.0f;

    const int ROWS = 128 + 2 * r + 8;
    const float* ip = g_sc1 + (size_t)s * PLANE;
    for (int i = tid; i < ROWS * 64; i += 512) {
        int rr = i >> 6, cc = i & 63;
        int gx = x0 - r + rr;
        stile[i] = ((unsigned)gx < WW) ? ip[(size_t)gx * HH + y0 + cc] : 0.0f;
    }
    __syncthreads();

    const u64* colp = (const u64*)stile + tx;
    const float* kk = sk + (RMAX - r);
    const int base = ty * 8;
    const int lenp = (2 * r + 4) & ~3;
    const int main8 = lenp & ~7;

    u64 w[8], acc[8];
    #pragma unroll
    for (int j = 0; j < 8; ++j) { w[j] = colp[(base + j) * 32]; acc[j] = zero2; }
    for (int u = 0; u < main8; u += 8) {
        #pragma unroll
        for (int uu = 0; uu < 8; ++uu) {
            u64 kv2 = pk2(kk[u + uu]);
            #pragma unroll
            for (int j = 0; j < 8; ++j) {
                u64 p = mul2(kv2, w[(uu + j) & 7]);          // rn(k*x)
                acc[j] = fma2(p, one2, acc[j]);              // rn(acc + p)
            }
            w[uu] = colp[(base + u + uu + 8) * 32];
        }
    }
    if (lenp & 4) {                     // 4-tap tail; phase 0
        #pragma unroll
        for (int uu = 0; uu < 4; ++uu) {
            u64 kv2 = pk2(kk[main8 + uu]);
            #pragma unroll
            for (int j = 0; j < 8; ++j) {
                u64 p = mul2(kv2, w[(uu + j) & 7]);          // rn(k*x)
                acc[j] = fma2(p, one2, acc[j]);              // rn(acc + p)
            }
            w[uu] = colp[(base + main8 + uu + 8) * 32];
        }
    }
    #pragma unroll
    for (int j = 0; j < 8; ++j) {
        stage[(2 * tx + 0) * 129 + ty * 8 + j] = lo2(acc[j]);
        stage[(2 * tx + 1) * 129 + ty * 8 + j] = hi2(acc[j]);
    }
    __syncthreads();
    float* op = g_sc2 + (size_t)s * PLANE + (size_t)y0 * WW + x0;
    for (int e = tid; e < 8192; e += 512) {
        int yo = e >> 7, xo = e & 127;   // consecutive e -> consecutive xo
        op[(size_t)yo * WW + xo] = stage[yo * 129 + xo];
    }
}

// ---------------------------------------------------------------------------
// Pass 3: fused DoG + 3x3x3 maxpool (pad -inf) + mask, rolling over scale s.
// ---------------------------------------------------------------------------
__global__ __launch_bounds__(256) void pass3_dog_nms(
    const float* __restrict__ sigmas, float* __restrict__ out,
    int S, size_t out_n)
{
    __shared__ float gb[2][34 * 36];
    __shared__ float db[2][34 * 36];
    __shared__ float m2[3][1024];

    const int tid = threadIdx.x;
    const int x0 = blockIdx.x * 32 - 1;
    const int y0 = blockIdx.y * 32 - 1;
    const float NINF = -INFINITY;
    const size_t n1 = (size_t)(S - 1) * PLANE;

    for (int i = tid; i < 3 * 1024; i += 256) (&m2[0][0])[i] = NINF;

    for (int s = 0; s <= S; ++s) {
        if (s < S) {
            const float* gp = g_sc2 + (size_t)s * PLANE;
            for (int i = tid; i < 34 * 34; i += 256) {
                int yy = i / 34, xx = i - yy * 34;
                int gy = y0 + yy, gx = x0 + xx;
                gb[s & 1][yy * 36 + xx] =
                    ((unsigned)gy < HH && (unsigned)gx < WW) ? gp[gy * WW + gx] : 0.0f;
            }
        }
        __syncthreads();
        if (s >= 1 && s < S) {
            float sg = sigmas[s - 1];
            for (int i = tid; i < 34 * 34; i += 256) {
                int yy = i / 34, xx = i - yy * 34;
                int gy = y0 + yy, gx = x0 + xx;
                float v = NINF;  // -inf outside image: matches maxpool padding
                if ((unsigned)gy < HH && (unsigned)gx < WW)
                    v = __fmul_rn(__fsub_rn(gb[(s - 1) & 1][yy * 36 + xx],
                                            gb[s & 1][yy * 36 + xx]), sg);
                db[(s - 1) & 1][yy * 36 + xx] = v;
            }
        } else if (s == S) {
            for (int i = tid; i < 1024; i += 256) m2[(S - 1) % 3][i] = NINF;
        }
        __syncthreads();
        if (s >= 1 && s < S) {
            int d = s - 1;
            const float* dp0 = &db[d & 1][0];
            for (int i = tid; i < 1024; i += 256) {
                int yy = i >> 5, xx = i & 31;
                const float* dp = dp0 + yy * 36 + xx;
                float m = fmaxf(fmaxf(dp[0], dp[1]), dp[2]);
                m = fmaxf(m, fmaxf(fmaxf(dp[36], dp[37]), dp[38]));
                m = fmaxf(m, fmaxf(fmaxf(dp[72], dp[73]), dp[74]));
                m2[d % 3][i] = m;
            }
        }
        __syncthreads();
        if (s >= 2) {
            int t = s - 2;
            for (int i = tid; i < 1024; i += 256) {
                int yy = i >> 5, xx = i & 31;
                float dv = db[t & 1][(yy + 1) * 36 + (xx + 1)];
                float p = fmaxf(fmaxf(m2[(t + 2) % 3][i], m2[t % 3][i]),
                                m2[(t + 1) % 3][i]);
                int gy = y0 + 1 + yy, gx = x0 + 1 + xx;
                size_t oidx = (size_t)t * PLANE + (size_t)gy * WW + gx;
                if (oidx < out_n) out[oidx] = dv;
                size_t midx = n1 + oidx;
                if (midx < out_n)
                    out[midx] = (dv == p && dv > 0.001f) ? 1.0f : 0.0f;
            }
        }
        __syncthreads();
    }
}

__global__ void zero_tail(float* p, size_t n)
{
    size_t i = (size_t)blockIdx.x * blockDim.x + threadIdx.x;
    if (i < n) p[i] = 0.0f;
}

extern "C" void kernel_launch(void* const* d_in, const int* in_sizes, int n_in,
                              void* d_out, int out_size)
{
    const float* img = (const float*)d_in[0];
    const float* k1  = (const float*)d_in[1];
    const float* sig = (const float*)d_in[2];
    int S = in_sizes[2];               // number of sigmas
    int K = in_sizes[1] / S;           // padded 1D kernel length
    int RMAX = (K - 1) / 2;
    float* out = (float*)d_out;
    size_t n1 = (size_t)(S - 1) * PLANE;
    size_t used = 2 * n1;
    size_t on = (size_t)out_size;

    int rows = 128 + 2 * RMAX + 8;
    size_t smem1 = (size_t)(256 + rows * 64 + 64 * 129) * sizeof(float);
    size_t smem2 = (size_t)(128 + rows * 64 + 64 * 129) * sizeof(float);
    cudaFuncSetAttribute(pass1_vert, cudaFuncAttributeMaxDynamicSharedMemorySize,
                         (int)smem1);
    cudaFuncSetAttribute(pass2_horiz, cudaFuncAttributeMaxDynamicSharedMemorySize,
                         (int)smem2);

    const int NZ = 7;                  // 896 blocks = 3.03 waves at 2/SM
    dim3 g1(WW / 64, HH / 128, NZ);
    pass1_vert<<<g1, 512, smem1>>>(img, k1, sig, S, K, RMAX, NZ);

    // zero_rt/one_rt as runtime args: opaque to constant folding.
    volatile float z = 0.0f, o = 1.0f;
    dim3 g2(HH / 64, WW / 128, S);     // R12 dispatch order (y-tile fastest)
    pass2_horiz<<<g2, 512, smem2>>>(k1, sig, S, K, RMAX, z, o);

    dim3 g3(WW / 32, HH / 32);
    pass3_dog_nms<<<g3, 256>>>(sig, out, S, on);

    if (on > used) {
        size_t rem = on - used;
        int blocks = (int)((rem + 255) / 256);
        zero_tail<<<blocks, 256>>>(out + used, rem);
    }
}

// round 16
// speedup vs baseline: 1.2725x; 1.0669x over previous
#include <cuda_runtime.h>
#include <math.h>

#define HH 1024
#define WW 1024
#define PLANE (HH * WW)

typedef unsigned long long u64;

// Scratch: pass1 output (transposed, [s][x][y]) and pass2 output ([s][y][x]).
__device__ float g_sc1[(size_t)52 * PLANE];
__device__ float g_sc2[(size_t)52 * PLANE];

// ---- packed f32x2 helpers (two independent IEEE-RN lane ops per instr) ----
__device__ __forceinline__ u64 pk2(float v) {
    u64 r; asm("mov.b64 %0, {%1, %1};" : "=l"(r) : "f"(v)); return r;
}
__device__ __forceinline__ u64 fma2(u64 a, u64 b, u64 c) {   // per-lane __fmaf_rn
    u64 d; asm("fma.rn.f32x2 %0, %1, %2, %3;" : "=l"(d) : "l"(a), "l"(b), "l"(c));
    return d;
}
__device__ __forceinline__ u64 mul2(u64 a, u64 b) {          // per-lane __fmul_rn
    u64 d; asm("mul.rn.f32x2 %0, %1, %2;" : "=l"(d) : "l"(a), "l"(b)); return d;
}
__device__ __forceinline__ float lo2(u64 v) { return __uint_as_float((unsigned)v); }
__device__ __forceinline__ float hi2(u64 v) { return __uint_as_float((unsigned)(v >> 32)); }

// ---------------------------------------------------------------------------
// Pass 1: vertical conv, FMA numerics (ascending taps, single accumulator).
// 512 threads, tile 64x x 128y; thread = x-pair (2*tx) x 8 y-outputs (f32x2).
// lenp multiple of 4 (main 8-groups + optional 4-tail, phase 0; pads hit k==0).
// Sigma classes strided (s = c, c+NZ, ...); strip double-buffer by it parity.
// Output transposed to g_sc1[s][x][y] via smem stage.
// ---------------------------------------------------------------------------
__global__ __launch_bounds__(512, 2) void pass1_vert(
    const float* __restrict__ img, const float* __restrict__ k1,
    const float* __restrict__ sigmas, int S, int K, int RMAX, int NZ)
{
    extern __shared__ float sm[];
    float* skb = sm;                       // 2 * 128 kernel strips
    float* simg = sm + 256;                // ROWS * 64
    const int ROWS = 128 + 2 * RMAX + 8;
    float* stage = simg + ROWS * 64;       // 64 * 129 (stage[x][y])

    const int tid = threadIdx.x;
    const int tx = tid & 31, ty = tid >> 5;          // ty in 0..15
    const int x0 = blockIdx.x * 64;
    const int y0 = blockIdx.y * 128;
    const int c = blockIdx.z;                        // sigma stride class

    for (int i = tid; i < 128; i += 512) skb[i] = (i < K) ? k1[c * K + i] : 0.0f;
    for (int i = tid; i < ROWS * 64; i += 512) {
        int rr = i >> 6, cc = i & 63;
        int gy = y0 - RMAX + rr;
        simg[i] = ((unsigned)gy < HH) ? img[gy * WW + x0 + cc] : 0.0f;
    }
    __syncthreads();

    const u64* colp = (const u64*)simg + tx;   // 32 u64 per row

    int it = 0;
    for (int s = c; s < S; s += NZ, ++it) {
        if (s + NZ < S) {
            float* nb = skb + ((it + 1) & 1) * 128;
            for (int i = tid; i < 128; i += 512)
                nb[i] = (i < K) ? k1[(s + NZ) * K + i] : 0.0f;
        }

        float sg = sigmas[s];
        int r = (int)(5.0f * sg + 0.5f) + 1;
        if (r > RMAX) r = RMAX;
        const int lenp = (2 * r + 4) & ~3;          // mult of 4; pads hit k==0
        const int main8 = lenp & ~7;
        const float* kk = skb + (it & 1) * 128 + (RMAX - r);
        const int base = ty * 8 + (RMAX - r);

        u64 w[8], acc[8];
        #pragma unroll
        for (int j = 0; j < 8; ++j) { w[j] = colp[(base + j) * 32]; acc[j] = 0ull; }
        for (int u = 0; u < main8; u += 8) {
            #pragma unroll
            for (int uu = 0; uu < 8; ++uu) {
                u64 kv2 = pk2(kk[u + uu]);
                #pragma unroll
                for (int j = 0; j < 8; ++j)
                    acc[j] = fma2(kv2, w[(uu + j) & 7], acc[j]);
                w[uu] = colp[(base + u + uu + 8) * 32];
            }
        }
        if (lenp & 4) {                 // 4-tap tail; phase 0 (main8 % 8 == 0)
            #pragma unroll
            for (int uu = 0; uu < 4; ++uu) {
                u64 kv2 = pk2(kk[main8 + uu]);
                #pragma unroll
                for (int j = 0; j < 8; ++j)
                    acc[j] = fma2(kv2, w[(uu + j) & 7], acc[j]);
                w[uu] = colp[(base + main8 + uu + 8) * 32];
            }
        }
        __syncthreads();   // prior stage reads done; strip prefetch visible next iter
        #pragma unroll
        for (int j = 0; j < 8; ++j) {
            stage[(2 * tx + 0) * 129 + ty * 8 + j] = lo2(acc[j]);
            stage[(2 * tx + 1) * 129 + ty * 8 + j] = hi2(acc[j]);
        }
        __syncthreads();
        float* op = g_sc1 + (size_t)s * PLANE + (size_t)x0 * HH + y0;
        for (int e = tid; e < 8192; e += 512) {
            int xo = e >> 7, yo = e & 127;   // consecutive e -> consecutive yo
            op[(size_t)xo * HH + yo] = stage[xo * 129 + yo];
        }
    }
}

// ---------------------------------------------------------------------------
// Pass 2: horizontal conv on transposed planes, STRICT mul-then-add numerics
// (two roundings per tap):
//   p   = mul.rn.f32x2(k, x)        == rn(k*x)
//   acc = fma.rn.f32x2(p, one, acc) == rn(acc + p) (x1 exact; FMA consumer =>
//                                                   no mul+add contraction)
// one is a runtime arg so ptxas cannot fold the FMA into an ADD.
// 512 threads; tile 64 minor(y) x 128 conv(x); thread = y-pair x 8 x-outputs.
// Output [s][y][x] via smem stage. y-tile-fastest dispatch (measured best).
// ---------------------------------------------------------------------------
__global__ __launch_bounds__(512, 2) void pass2_horiz(
    const float* __restrict__ k1, const float* __restrict__ sigmas,
    int S, int K, int RMAX, float zero_rt, float one_rt)
{
    extern __shared__ float sm[];
    float* sk = sm;                        // 128
    float* stile = sm + 128;               // (128 + 2*RMAX + 8) * 64
    float* stage = stile + (128 + 2 * RMAX + 8) * 64;  // 64 * 129 (stage[y][x])

    const int tid = threadIdx.x;
    const int tx = tid & 31, ty = tid >> 5;
    const int y0 = blockIdx.x * 64;   // minor dim of transposed layout
    const int x0 = blockIdx.y * 128;  // conv dim
    const int s = blockIdx.z;

    const u64 zero2 = pk2(zero_rt);
    const u64 one2 = pk2(one_rt);

    float sg = sigmas[s];
    int r = (int)(5.0f * sg + 0.5f) + 1;
    if (r > RMAX) r = RMAX;

    for (int i = tid; i < 128; i += 512) sk[i] = (i < K) ? k1[s * K + i] : 0.0f;

    const int ROWS = 128 + 2 * r + 8;
    const float* ip = g_sc1 + (size_t)s * PLANE;
    for (int i = tid; i < ROWS * 64; i += 512) {
        int rr = i >> 6, cc = i & 63;
        int gx = x0 - r + rr;
        stile[i] = ((unsigned)gx < WW) ? ip[(size_t)gx * HH + y0 + cc] : 0.0f;
    }
    __syncthreads();

    const u64* colp = (const u64*)stile + tx;
    const float* kk = sk + (RMAX - r);
    const int base = ty * 8;
    const int lenp = (2 * r + 4) & ~3;
    const int main8 = lenp & ~7;

    u64 w[8], acc[8];
    #pragma unroll
    for (int j = 0; j < 8; ++j) { w[j] = colp[(base + j) * 32]; acc[j] = zero2; }
    for (int u = 0; u < main8; u += 8) {
        #pragma unroll
        for (int uu = 0; uu < 8; ++uu) {
            u64 kv2 = pk2(kk[u + uu]);
            #pragma unroll
            for (int j = 0; j < 8; ++j) {
                u64 p = mul2(kv2, w[(uu + j) & 7]);          // rn(k*x)
                acc[j] = fma2(p, one2, acc[j]);              // rn(acc + p)
            }
            w[uu] = colp[(base + u + uu + 8) * 32];
        }
    }
    if (lenp & 4) {                     // 4-tap tail; phase 0
        #pragma unroll
        for (int uu = 0; uu < 4; ++uu) {
            u64 kv2 = pk2(kk[main8 + uu]);
            #pragma unroll
            for (int j = 0; j < 8; ++j) {
                u64 p = mul2(kv2, w[(uu + j) & 7]);          // rn(k*x)
                acc[j] = fma2(p, one2, acc[j]);              // rn(acc + p)
            }
            w[uu] = colp[(base + main8 + uu + 8) * 32];
        }
    }
    #pragma unroll
    for (int j = 0; j < 8; ++j) {
        stage[(2 * tx + 0) * 129 + ty * 8 + j] = lo2(acc[j]);
        stage[(2 * tx + 1) * 129 + ty * 8 + j] = hi2(acc[j]);
    }
    __syncthreads();
    float* op = g_sc2 + (size_t)s * PLANE + (size_t)y0 * WW + x0;
    for (int e = tid; e < 8192; e += 512) {
        int yo = e >> 7, xo = e & 127;   // consecutive e -> consecutive xo
        op[(size_t)yo * WW + xo] = stage[yo * 129 + xo];
    }
}

// ---------------------------------------------------------------------------
// Pass 3: fused DoG + 3x3x3 maxpool (pad -inf) + mask, rolling over scale s.
// Restructured: gb smem ELIDED (DoG is elementwise; each thread keeps its 5
// loaded plane values in prev[] registers) -> db written at load time,
// 3 barriers/iter instead of 4. All index maps hoisted out of the s-loop.
// Same values, same NINF padding, same m2 rotation as before.
// ---------------------------------------------------------------------------
__global__ __launch_bounds__(256) void pass3_dog_nms(
    const float* __restrict__ sigmas, float* __restrict__ out,
    int S, size_t out_n)
{
    __shared__ float db[2][34 * 36];
    __shared__ float m2[3][1024];

    const int tid = threadIdx.x;
    const int x0 = blockIdx.x * 32 - 1;
    const int y0 = blockIdx.y * 32 - 1;
    const float NINF = -INFINITY;
    const size_t n1 = (size_t)(S - 1) * PLANE;

    // ---- hoisted load-slot maps (identical every iteration) ----
    int   l_sidx[5];   size_t l_goff[5];   bool l_ok[5];   int nslot = 0;
    #pragma unroll
    for (int v = 0; v < 5; ++v) {
        int i = tid + v * 256;
        if (i < 34 * 34) {
            int yy = i / 34, xx = i - yy * 34;
            int gy = y0 + yy, gx = x0 + xx;
            bool ok = ((unsigned)gy < HH) && ((unsigned)gx < WW);
            l_sidx[nslot] = yy * 36 + xx;
            l_goff[nslot] = ok ? ((size_t)gy * WW + gx) : 0;
            l_ok[nslot] = ok;
            ++nslot;
        }
    }
    // ---- hoisted emit-slot maps (4 slots, exact) ----
    int e_dbc[4]; size_t e_off[4];
    #pragma unroll
    for (int v = 0; v < 4; ++v) {
        int i = tid + v * 256;
        int yy = i >> 5, xx = i & 31;
        e_dbc[v] = (yy + 1) * 36 + (xx + 1);
        e_off[v] = (size_t)(y0 + 1 + yy) * WW + (x0 + 1 + xx);
    }

    float prev[5];

    for (int i = tid; i < 3 * 1024; i += 256) (&m2[0][0])[i] = NINF;

    for (int s = 0; s <= S; ++s) {
        if (s < S) {
            const float* gp = g_sc2 + (size_t)s * PLANE;
            if (s == 0) {
                #pragma unroll
                for (int v = 0; v < 5; ++v)
                    if (v < nslot) prev[v] = l_ok[v] ? gp[l_goff[v]] : 0.0f;
            } else {
                float sg = sigmas[s - 1];
                float* dbw = &db[(s - 1) & 1][0];
                #pragma unroll
                for (int v = 0; v < 5; ++v)
                    if (v < nslot) {
                        float cur = l_ok[v] ? gp[l_goff[v]] : 0.0f;
                        dbw[l_sidx[v]] = l_ok[v]
                            ? __fmul_rn(__fsub_rn(prev[v], cur), sg) : NINF;
                        prev[v] = cur;
                    }
            }
        } else {
            // flush: dog[S-1] doesn't exist; neutralize its (stale) m2 slot
            for (int i = tid; i < 1024; i += 256) m2[(S - 1) % 3][i] = NINF;
        }
        __syncthreads();
        if (s >= 1 && s < S) {
            int d = s - 1;
            const float* dp0 = &db[d & 1][0];
            for (int i = tid; i < 1024; i += 256) {
                int yy = i >> 5, xx = i & 31;
                const float* dp = dp0 + yy * 36 + xx;
                float m = fmaxf(fmaxf(dp[0], dp[1]), dp[2]);
                m = fmaxf(m, fmaxf(fmaxf(dp[36], dp[37]), dp[38]));
                m = fmaxf(m, fmaxf(fmaxf(dp[72], dp[73]), dp[74]));
                m2[d % 3][i] = m;
            }
        }
        __syncthreads();
        if (s >= 2) {
            int t = s - 2;
            const float* dbr = &db[t & 1][0];
            const float* m2a = &m2[(t + 2) % 3][0];
            const float* m2b = &m2[t % 3][0];
            const float* m2c = &m2[(t + 1) % 3][0];
            size_t tbase = (size_t)t * PLANE;
            #pragma unroll
            for (int v = 0; v < 4; ++v) {
                int i = tid + v * 256;
                float dv = dbr[e_dbc[v]];
                float p = fmaxf(fmaxf(m2a[i], m2b[i]), m2c[i]);
                size_t oidx = tbase + e_off[v];
                if (oidx < out_n) out[oidx] = dv;
                size_t midx = n1 + oidx;
                if (midx < out_n)
                    out[midx] = (dv == p && dv > 0.001f) ? 1.0f : 0.0f;
            }
        }
        __syncthreads();
    }
}

__global__ void zero_tail(float* p, size_t n)
{
    size_t i = (size_t)blockIdx.x * blockDim.x + threadIdx.x;
    if (i < n) p[i] = 0.0f;
}

extern "C" void kernel_launch(void* const* d_in, const int* in_sizes, int n_in,
                              void* d_out, int out_size)
{
    const float* img = (const float*)d_in[0];
    const float* k1  = (const float*)d_in[1];
    const float* sig = (const float*)d_in[2];
    int S = in_sizes[2];               // number of sigmas
    int K = in_sizes[1] / S;           // padded 1D kernel length
    int RMAX = (K - 1) / 2;
    float* out = (float*)d_out;
    size_t n1 = (size_t)(S - 1) * PLANE;
    size_t used = 2 * n1;
    size_t on = (size_t)out_size;

    int rows = 128 + 2 * RMAX + 8;
    size_t smem1 = (size_t)(256 + rows * 64 + 64 * 129) * sizeof(float);
    size_t smem2 = (size_t)(128 + rows * 64 + 64 * 129) * sizeof(float);
    cudaFuncSetAttribute(pass1_vert, cudaFuncAttributeMaxDynamicSharedMemorySize,
                         (int)smem1);
    cudaFuncSetAttribute(pass2_horiz, cudaFuncAttributeMaxDynamicSharedMemorySize,
                         (int)smem2);

    const int NZ = 7;                  // 896 blocks = 3.03 waves at 2/SM
    dim3 g1(WW / 64, HH / 128, NZ);
    pass1_vert<<<g1, 512, smem1>>>(img, k1, sig, S, K, RMAX, NZ);

    // zero_rt/one_rt as runtime args: opaque to constant folding.
    volatile float z = 0.0f, o = 1.0f;
    dim3 g2(HH / 64, WW / 128, S);     // y-tile fastest (measured best)
    pass2_horiz<<<g2, 512, smem2>>>(k1, sig, S, K, RMAX, z, o);

    dim3 g3(WW / 32, HH / 32);
    pass3_dog_nms<<<g3, 256>>>(sig, out, S, on);

    if (on > used) {
        size_t rem = on - used;
        int blocks = (int)((rem + 255) / 256);
        zero_tail<<<blocks, 256>>>(out + used, rem);
    }
}

// round 17
// speedup vs baseline: 1.2857x; 1.0103x over previous
#include <cuda_runtime.h>
#include <math.h>

#define HH 1024
#define WW 1024
#define PLANE (HH * WW)

typedef unsigned long long u64;

// Scratch: pass1 output (transposed, [s][x][y]) and pass2 output ([s][y][x]).
__device__ float g_sc1[(size_t)52 * PLANE];
__device__ float g_sc2[(size_t)52 * PLANE];

// ---- packed f32x2 helpers (two independent IEEE-RN lane ops per instr) ----
__device__ __forceinline__ u64 pk2(float v) {
    u64 r; asm("mov.b64 %0, {%1, %1};" : "=l"(r) : "f"(v)); return r;
}
__device__ __forceinline__ u64 fma2(u64 a, u64 b, u64 c) {   // per-lane __fmaf_rn
    u64 d; asm("fma.rn.f32x2 %0, %1, %2, %3;" : "=l"(d) : "l"(a), "l"(b), "l"(c));
    return d;
}
__device__ __forceinline__ u64 mul2(u64 a, u64 b) {          // per-lane __fmul_rn
    u64 d; asm("mul.rn.f32x2 %0, %1, %2;" : "=l"(d) : "l"(a), "l"(b)); return d;
}
__device__ __forceinline__ float lo2(u64 v) { return __uint_as_float((unsigned)v); }
__device__ __forceinline__ float hi2(u64 v) { return __uint_as_float((unsigned)(v >> 32)); }

// ---------------------------------------------------------------------------
// Pass 1: vertical conv, FMA numerics (ascending taps, single accumulator).
// 512 threads, tile 64x x 128y; thread = x-pair (2*tx) x 8 y-outputs (f32x2).
// lenp multiple of 4 (main 8-groups + optional 4-tail, phase 0; pads hit k==0).
// Sigma classes strided (s = c, c+NZ, ...); strip double-buffer by it parity.
// Output transposed to g_sc1[s][x][y] via smem stage.
// ---------------------------------------------------------------------------
__global__ __launch_bounds__(512, 2) void pass1_vert(
    const float* __restrict__ img, const float* __restrict__ k1,
    const float* __restrict__ sigmas, int S, int K, int RMAX, int NZ)
{
    extern __shared__ float sm[];
    float* skb = sm;                       // 2 * 128 kernel strips
    float* simg = sm + 256;                // ROWS * 64
    const int ROWS = 128 + 2 * RMAX + 8;
    float* stage = simg + ROWS * 64;       // 64 * 129 (stage[x][y])

    const int tid = threadIdx.x;
    const int tx = tid & 31, ty = tid >> 5;          // ty in 0..15
    const int x0 = blockIdx.x * 64;
    const int y0 = blockIdx.y * 128;
    const int c = blockIdx.z;                        // sigma stride class

    for (int i = tid; i < 128; i += 512) skb[i] = (i < K) ? k1[c * K + i] : 0.0f;
    for (int i = tid; i < ROWS * 64; i += 512) {
        int rr = i >> 6, cc = i & 63;
        int gy = y0 - RMAX + rr;
        simg[i] = ((unsigned)gy < HH) ? img[gy * WW + x0 + cc] : 0.0f;
    }
    __syncthreads();

    const u64* colp = (const u64*)simg + tx;   // 32 u64 per row

    int it = 0;
    for (int s = c; s < S; s += NZ, ++it) {
        if (s + NZ < S) {
            float* nb = skb + ((it + 1) & 1) * 128;
            for (int i = tid; i < 128; i += 512)
                nb[i] = (i < K) ? k1[(s + NZ) * K + i] : 0.0f;
        }

        float sg = sigmas[s];
        int r = (int)(5.0f * sg + 0.5f) + 1;
        if (r > RMAX) r = RMAX;
        const int lenp = (2 * r + 4) & ~3;          // mult of 4; pads hit k==0
        const int main8 = lenp & ~7;
        const float* kk = skb + (it & 1) * 128 + (RMAX - r);
        const int base = ty * 8 + (RMAX - r);

        u64 w[8], acc[8];
        #pragma unroll
        for (int j = 0; j < 8; ++j) { w[j] = colp[(base + j) * 32]; acc[j] = 0ull; }
        for (int u = 0; u < main8; u += 8) {
            #pragma unroll
            for (int uu = 0; uu < 8; ++uu) {
                u64 kv2 = pk2(kk[u + uu]);
                #pragma unroll
                for (int j = 0; j < 8; ++j)
                    acc[j] = fma2(kv2, w[(uu + j) & 7], acc[j]);
                w[uu] = colp[(base + u + uu + 8) * 32];
            }
        }
        if (lenp & 4) {                 // 4-tap tail; phase 0 (main8 % 8 == 0)
            #pragma unroll
            for (int uu = 0; uu < 4; ++uu) {
                u64 kv2 = pk2(kk[main8 + uu]);
                #pragma unroll
                for (int j = 0; j < 8; ++j)
                    acc[j] = fma2(kv2, w[(uu + j) & 7], acc[j]);
                w[uu] = colp[(base + main8 + uu + 8) * 32];
            }
        }
        __syncthreads();   // prior stage reads done; strip prefetch visible next iter
        #pragma unroll
        for (int j = 0; j < 8; ++j) {
            stage[(2 * tx + 0) * 129 + ty * 8 + j] = lo2(acc[j]);
            stage[(2 * tx + 1) * 129 + ty * 8 + j] = hi2(acc[j]);
        }
        __syncthreads();
        float* op = g_sc1 + (size_t)s * PLANE + (size_t)x0 * HH + y0;
        for (int e = tid; e < 8192; e += 512) {
            int xo = e >> 7, yo = e & 127;   // consecutive e -> consecutive yo
            op[(size_t)xo * HH + yo] = stage[xo * 129 + yo];
        }
    }
}

// ---------------------------------------------------------------------------
// Pass 2: horizontal conv on transposed planes, STRICT mul-then-add numerics
// (two roundings per tap):
//   p   = mul.rn.f32x2(k, x)        == rn(k*x)
//   acc = fma.rn.f32x2(p, one, acc) == rn(acc + p) (x1 exact; FMA consumer =>
//                                                   no mul+add contraction)
// one is a runtime arg so ptxas cannot fold the FMA into an ADD.
// 512 threads; tile 64 minor(y) x 128 conv(x); thread = y-pair x 8 x-outputs.
// STAGE ALIASED into the tile buffer (tile reads complete before stage writes,
// separated by an extra barrier): smem 94KB -> 61KB, L1 carveout 40 -> 106KB.
// ---------------------------------------------------------------------------
__global__ __launch_bounds__(512, 2) void pass2_horiz(
    const float* __restrict__ k1, const float* __restrict__ sigmas,
    int S, int K, int RMAX, float zero_rt, float one_rt)
{
    extern __shared__ float sm[];
    float* sk = sm;                        // 128
    float* stile = sm + 128;               // (128 + 2*RMAX + 8) * 64
    float* stage = stile;                  // ALIAS: stage[y][x] reuses tile smem

    const int tid = threadIdx.x;
    const int tx = tid & 31, ty = tid >> 5;
    const int y0 = blockIdx.x * 64;   // minor dim of transposed layout
    const int x0 = blockIdx.y * 128;  // conv dim
    const int s = blockIdx.z;

    const u64 zero2 = pk2(zero_rt);
    const u64 one2 = pk2(one_rt);

    float sg = sigmas[s];
    int r = (int)(5.0f * sg + 0.5f) + 1;
    if (r > RMAX) r = RMAX;

    for (int i = tid; i < 128; i += 512) sk[i] = (i < K) ? k1[s * K + i] : 0.0f;

    const int ROWS = 128 + 2 * r + 8;
    const float* ip = g_sc1 + (size_t)s * PLANE;
    for (int i = tid; i < ROWS * 64; i += 512) {
        int rr = i >> 6, cc = i & 63;
        int gx = x0 - r + rr;
        stile[i] = ((unsigned)gx < WW) ? ip[(size_t)gx * HH + y0 + cc] : 0.0f;
    }
    __syncthreads();

    const u64* colp = (const u64*)stile + tx;
    const float* kk = sk + (RMAX - r);
    const int base = ty * 8;
    const int lenp = (2 * r + 4) & ~3;
    const int main8 = lenp & ~7;

    u64 w[8], acc[8];
    #pragma unroll
    for (int j = 0; j < 8; ++j) { w[j] = colp[(base + j) * 32]; acc[j] = zero2; }
    for (int u = 0; u < main8; u += 8) {
        #pragma unroll
        for (int uu = 0; uu < 8; ++uu) {
            u64 kv2 = pk2(kk[u + uu]);
            #pragma unroll
            for (int j = 0; j < 8; ++j) {
                u64 p = mul2(kv2, w[(uu + j) & 7]);          // rn(k*x)
                acc[j] = fma2(p, one2, acc[j]);              // rn(acc + p)
            }
            w[uu] = colp[(base + u + uu + 8) * 32];
        }
    }
    if (lenp & 4) {                     // 4-tap tail; phase 0
        #pragma unroll
        for (int uu = 0; uu < 4; ++uu) {
            u64 kv2 = pk2(kk[main8 + uu]);
            #pragma unroll
            for (int j = 0; j < 8; ++j) {
                u64 p = mul2(kv2, w[(uu + j) & 7]);          // rn(k*x)
                acc[j] = fma2(p, one2, acc[j]);              // rn(acc + p)
            }
            w[uu] = colp[(base + main8 + uu + 8) * 32];
        }
    }
    __syncthreads();   // ALL tile reads done before stage overwrites the buffer
    #pragma unroll
    for (int j = 0; j < 8; ++j) {
        stage[(2 * tx + 0) * 129 + ty * 8 + j] = lo2(acc[j]);
        stage[(2 * tx + 1) * 129 + ty * 8 + j] = hi2(acc[j]);
    }
    __syncthreads();
    float* op = g_sc2 + (size_t)s * PLANE + (size_t)y0 * WW + x0;
    for (int e = tid; e < 8192; e += 512) {
        int yo = e >> 7, xo = e & 127;   // consecutive e -> consecutive xo
        op[(size_t)yo * WW + xo] = stage[yo * 129 + xo];
    }
}

// ---------------------------------------------------------------------------
// Pass 3: fused DoG + 3x3x3 maxpool (pad -inf) + mask, rolling over scale s.
// gb smem elided (prev[] registers); 3 barriers/iter; index maps hoisted.
// ---------------------------------------------------------------------------
__global__ __launch_bounds__(256) void pass3_dog_nms(
    const float* __restrict__ sigmas, float* __restrict__ out,
    int S, size_t out_n)
{
    __shared__ float db[2][34 * 36];
    __shared__ float m2[3][1024];

    const int tid = threadIdx.x;
    const int x0 = blockIdx.x * 32 - 1;
    const int y0 = blockIdx.y * 32 - 1;
    const float NINF = -INFINITY;
    const size_t n1 = (size_t)(S - 1) * PLANE;

    int   l_sidx[5];   size_t l_goff[5];   bool l_ok[5];   int nslot = 0;
    #pragma unroll
    for (int v = 0; v < 5; ++v) {
        int i = tid + v * 256;
        if (i < 34 * 34) {
            int yy = i / 34, xx = i - yy * 34;
            int gy = y0 + yy, gx = x0 + xx;
            bool ok = ((unsigned)gy < HH) && ((unsigned)gx < WW);
            l_sidx[nslot] = yy * 36 + xx;
            l_goff[nslot] = ok ? ((size_t)gy * WW + gx) : 0;
            l_ok[nslot] = ok;
            ++nslot;
        }
    }
    int e_dbc[4]; size_t e_off[4];
    #pragma unroll
    for (int v = 0; v < 4; ++v) {
        int i = tid + v * 256;
        int yy = i >> 5, xx = i & 31;
        e_dbc[v] = (yy + 1) * 36 + (xx + 1);
        e_off[v] = (size_t)(y0 + 1 + yy) * WW + (x0 + 1 + xx);
    }

    float prev[5];

    for (int i = tid; i < 3 * 1024; i += 256) (&m2[0][0])[i] = NINF;

    for (int s = 0; s <= S; ++s) {
        if (s < S) {
            const float* gp = g_sc2 + (size_t)s * PLANE;
            if (s == 0) {
                #pragma unroll
                for (int v = 0; v < 5; ++v)
                    if (v < nslot) prev[v] = l_ok[v] ? gp[l_goff[v]] : 0.0f;
            } else {
                float sg = sigmas[s - 1];
                float* dbw = &db[(s - 1) & 1][0];
                #pragma unroll
                for (int v = 0; v < 5; ++v)
                    if (v < nslot) {
                        float cur = l_ok[v] ? gp[l_goff[v]] : 0.0f;
                        dbw[l_sidx[v]] = l_ok[v]
                            ? __fmul_rn(__fsub_rn(prev[v], cur), sg) : NINF;
                        prev[v] = cur;
                    }
            }
        } else {
            for (int i = tid; i < 1024; i += 256) m2[(S - 1) % 3][i] = NINF;
        }
        __syncthreads();
        if (s >= 1 && s < S) {
            int d = s - 1;
            const float* dp0 = &db[d & 1][0];
            for (int i = tid; i < 1024; i += 256) {
                int yy = i >> 5, xx = i & 31;
                const float* dp = dp0 + yy * 36 + xx;
                float m = fmaxf(fmaxf(dp[0], dp[1]), dp[2]);
                m = fmaxf(m, fmaxf(fmaxf(dp[36], dp[37]), dp[38]));
                m = fmaxf(m, fmaxf(fmaxf(dp[72], dp[73]), dp[74]));
                m2[d % 3][i] = m;
            }
        }
        __syncthreads();
        if (s >= 2) {
            int t = s - 2;
            const float* dbr = &db[t & 1][0];
            const float* m2a = &m2[(t + 2) % 3][0];
            const float* m2b = &m2[t % 3][0];
            const float* m2c = &m2[(t + 1) % 3][0];
            size_t tbase = (size_t)t * PLANE;
            #pragma unroll
            for (int v = 0; v < 4; ++v) {
                int i = tid + v * 256;
                float dv = dbr[e_dbc[v]];
                float p = fmaxf(fmaxf(m2a[i], m2b[i]), m2c[i]);
                size_t oidx = tbase + e_off[v];
                if (oidx < out_n) out[oidx] = dv;
                size_t midx = n1 + oidx;
                if (midx < out_n)
                    out[midx] = (dv == p && dv > 0.001f) ? 1.0f : 0.0f;
            }
        }
        __syncthreads();
    }
}

__global__ void zero_tail(float* p, size_t n)
{
    size_t i = (size_t)blockIdx.x * blockDim.x + threadIdx.x;
    if (i < n) p[i] = 0.0f;
}

extern "C" void kernel_launch(void* const* d_in, const int* in_sizes, int n_in,
                              void* d_out, int out_size)
{
    const float* img = (const float*)d_in[0];
    const float* k1  = (const float*)d_in[1];
    const float* sig = (const float*)d_in[2];
    int S = in_sizes[2];               // number of sigmas
    int K = in_sizes[1] / S;           // padded 1D kernel length
    int RMAX = (K - 1) / 2;
    float* out = (float*)d_out;
    size_t n1 = (size_t)(S - 1) * PLANE;
    size_t used = 2 * n1;
    size_t on = (size_t)out_size;

    int rows = 128 + 2 * RMAX + 8;
    size_t smem1 = (size_t)(256 + rows * 64 + 64 * 129) * sizeof(float);
    size_t smem2 = (size_t)(128 + rows * 64) * sizeof(float);   // stage aliased
    cudaFuncSetAttribute(pass1_vert, cudaFuncAttributeMaxDynamicSharedMemorySize,
                         (int)smem1);
    cudaFuncSetAttribute(pass2_horiz, cudaFuncAttributeMaxDynamicSharedMemorySize,
                         (int)smem2);

    const int NZ = 7;                  // 896 blocks = 3.03 waves at 2/SM
    dim3 g1(WW / 64, HH / 128, NZ);
    pass1_vert<<<g1, 512, smem1>>>(img, k1, sig, S, K, RMAX, NZ);

    // zero_rt/one_rt as runtime args: opaque to constant folding.
    volatile float z = 0.0f, o = 1.0f;
    dim3 g2(HH / 64, WW / 128, S);     // y-tile fastest (measured best)
    pass2_horiz<<<g2, 512, smem2>>>(k1, sig, S, K, RMAX, z, o);

    dim3 g3(WW / 32, HH / 32);
    pass3_dog_nms<<<g3, 256>>>(sig, out, S, on);

    if (on > used) {
        size_t rem = on - used;
        int blocks = (int)((rem + 255) / 256);
        zero_tail<<<blocks, 256>>>(out + used, rem);
    }
}